// round 1
// baseline (speedup 1.0000x reference)
#include <cuda_runtime.h>
#include <cuda_bf16.h>

// Problem constants
#define BATCH 2
#define CCH   128
#define HH    56
#define WW    56
#define NPIX  3136          // 56*56
#define NH    4
#define HD    32
#define SCALE 0.17677669529663687f  // 1/sqrt(32)

// Scratch (allocation-free: __device__ globals)
__device__ float g_qkv[BATCH * 3 * CCH * NPIX];   // [b][3C][N]
__device__ float g_att[BATCH * CCH * NPIX];       // attention output [b][c][n]
__device__ float g_pre[BATCH * CCH * NPIX];       // att + lepe, pre-proj

// ---------------------------------------------------------------------------
// 1x1-conv GEMM: Y[b][o][n] = sum_c W[o][c] * X[b][c][n] + bias[o]
// K fixed at 128. Block: 256 threads computing a 64(o) x 64(n) tile, 4x4/thread.
// Smem tiles stored transposed (k-major) so the inner loop is 2x LDS.128 + 16 FMA.
// ---------------------------------------------------------------------------
__global__ __launch_bounds__(256) void gemm1x1_kernel(
    const float* __restrict__ W,     // [MO][128]
    const float* __restrict__ bias,  // [MO]
    const float* __restrict__ X,     // [B][128][N]
    float* __restrict__ Y,           // [B][MO][N]
    int MO)
{
    __shared__ float Wt[32][68];   // [k][o]
    __shared__ float Xs[32][68];   // [k][n]

    const int n0 = blockIdx.x * 64;
    const int o0 = blockIdx.y * 64;
    const int b  = blockIdx.z;
    const float* Xb = X + (size_t)b * CCH * NPIX;
    float* Yb = Y + (size_t)b * MO * NPIX;

    const int tid = threadIdx.x;
    const int tx = tid & 15;    // n direction (4 cols each)
    const int ty = tid >> 4;    // o direction (4 rows each)

    float acc[4][4];
#pragma unroll
    for (int i = 0; i < 4; i++)
#pragma unroll
        for (int j = 0; j < 4; j++) acc[i][j] = 0.f;

    for (int c0 = 0; c0 < 128; c0 += 32) {
        __syncthreads();
        {
            const int kc = tid & 31, r0 = tid >> 5;
#pragma unroll
            for (int e = 0; e < 8; e++) {
                int r = r0 + e * 8;
                Wt[kc][r] = W[(o0 + r) * 128 + c0 + kc];
            }
            const int n = tid & 63, k0 = tid >> 6;
#pragma unroll
            for (int e = 0; e < 8; e++) {
                int kc2 = k0 + e * 4;
                Xs[kc2][n] = Xb[(c0 + kc2) * NPIX + n0 + n];
            }
        }
        __syncthreads();
#pragma unroll
        for (int kc = 0; kc < 32; kc++) {
            float4 a = *(const float4*)&Wt[kc][ty * 4];
            float4 v = *(const float4*)&Xs[kc][tx * 4];
            acc[0][0] = fmaf(a.x, v.x, acc[0][0]);
            acc[0][1] = fmaf(a.x, v.y, acc[0][1]);
            acc[0][2] = fmaf(a.x, v.z, acc[0][2]);
            acc[0][3] = fmaf(a.x, v.w, acc[0][3]);
            acc[1][0] = fmaf(a.y, v.x, acc[1][0]);
            acc[1][1] = fmaf(a.y, v.y, acc[1][1]);
            acc[1][2] = fmaf(a.y, v.z, acc[1][2]);
            acc[1][3] = fmaf(a.y, v.w, acc[1][3]);
            acc[2][0] = fmaf(a.z, v.x, acc[2][0]);
            acc[2][1] = fmaf(a.z, v.y, acc[2][1]);
            acc[2][2] = fmaf(a.z, v.z, acc[2][2]);
            acc[2][3] = fmaf(a.z, v.w, acc[2][3]);
            acc[3][0] = fmaf(a.w, v.x, acc[3][0]);
            acc[3][1] = fmaf(a.w, v.y, acc[3][1]);
            acc[3][2] = fmaf(a.w, v.z, acc[3][2]);
            acc[3][3] = fmaf(a.w, v.w, acc[3][3]);
        }
    }

#pragma unroll
    for (int i = 0; i < 4; i++) {
        float bz = bias[o0 + ty * 4 + i];
        float4 out;
        out.x = acc[i][0] + bz;
        out.y = acc[i][1] + bz;
        out.z = acc[i][2] + bz;
        out.w = acc[i][3] + bz;
        *(float4*)&Yb[(size_t)(o0 + ty * 4 + i) * NPIX + n0 + tx * 4] = out;
    }
}

// ---------------------------------------------------------------------------
// Flash attention: grid (49, B*nh), 256 threads, BM=64 queries, BN=64 keys/iter.
// All smem tiles are d-major ([dim][pos]) matching the global [d][n] layout, so
// every inner-loop operand is an LDS.128 (or broadcast).
// ---------------------------------------------------------------------------
__global__ __launch_bounds__(256) void attn_kernel(float* __restrict__ Oout)
{
    __shared__ float Qt[32][68];   // [d][row]
    __shared__ float Kt[32][68];   // [d][col]
    __shared__ float Vt[32][68];   // [d][col]
    __shared__ float Ps[64][68];   // [row][col]  (reused for output staging)

    const int bz = blockIdx.y;
    const int b = bz >> 2, h = bz & 3;
    const float* Qg = g_qkv + (size_t)(b * 384 + h * 32) * NPIX;
    const float* Kg = g_qkv + (size_t)(b * 384 + 128 + h * 32) * NPIX;
    const float* Vg = g_qkv + (size_t)(b * 384 + 256 + h * 32) * NPIX;
    const int n0 = blockIdx.x * 64;

    const int tid = threadIdx.x;
    const int tx = tid & 15;     // 4 S-cols / 2 O-cols
    const int ty = tid >> 4;     // 4 rows

    // Q tile (scale folded in)
    {
        const int r = tid & 63, d0 = tid >> 6;
#pragma unroll
        for (int e = 0; e < 8; e++) {
            int d = d0 + e * 4;
            Qt[d][r] = Qg[d * NPIX + n0 + r] * SCALE;
        }
    }

    float m_i[4], l_i[4], o0a[4], o1a[4];
#pragma unroll
    for (int i = 0; i < 4; i++) { m_i[i] = -1e30f; l_i[i] = 0.f; o0a[i] = 0.f; o1a[i] = 0.f; }

    for (int t = 0; t < 49; t++) {
        __syncthreads();   // previous-iter smem reads done
        {
            const int c0 = t * 64;
            const int r = tid & 63, d0 = tid >> 6;
#pragma unroll
            for (int e = 0; e < 8; e++) {
                int d = d0 + e * 4;
                Kt[d][r] = Kg[d * NPIX + c0 + r];
                Vt[d][r] = Vg[d * NPIX + c0 + r];
            }
        }
        __syncthreads();

        // --- S = (scaled Q)^T K, 4x4 per thread ---
        float s[4][4];
#pragma unroll
        for (int i = 0; i < 4; i++)
#pragma unroll
            for (int j = 0; j < 4; j++) s[i][j] = 0.f;

#pragma unroll
        for (int d = 0; d < 32; d++) {
            float4 q = *(const float4*)&Qt[d][ty * 4];
            float4 k = *(const float4*)&Kt[d][tx * 4];
            s[0][0] = fmaf(q.x, k.x, s[0][0]);
            s[0][1] = fmaf(q.x, k.y, s[0][1]);
            s[0][2] = fmaf(q.x, k.z, s[0][2]);
            s[0][3] = fmaf(q.x, k.w, s[0][3]);
            s[1][0] = fmaf(q.y, k.x, s[1][0]);
            s[1][1] = fmaf(q.y, k.y, s[1][1]);
            s[1][2] = fmaf(q.y, k.z, s[1][2]);
            s[1][3] = fmaf(q.y, k.w, s[1][3]);
            s[2][0] = fmaf(q.z, k.x, s[2][0]);
            s[2][1] = fmaf(q.z, k.y, s[2][1]);
            s[2][2] = fmaf(q.z, k.z, s[2][2]);
            s[2][3] = fmaf(q.z, k.w, s[2][3]);
            s[3][0] = fmaf(q.w, k.x, s[3][0]);
            s[3][1] = fmaf(q.w, k.y, s[3][1]);
            s[3][2] = fmaf(q.w, k.z, s[3][2]);
            s[3][3] = fmaf(q.w, k.w, s[3][3]);
        }

        // --- online softmax per row (reduce over the 16 tx threads, width=16) ---
#pragma unroll
        for (int i = 0; i < 4; i++) {
            float rm = fmaxf(fmaxf(s[i][0], s[i][1]), fmaxf(s[i][2], s[i][3]));
            rm = fmaxf(rm, __shfl_xor_sync(0xffffffffu, rm, 1, 16));
            rm = fmaxf(rm, __shfl_xor_sync(0xffffffffu, rm, 2, 16));
            rm = fmaxf(rm, __shfl_xor_sync(0xffffffffu, rm, 4, 16));
            rm = fmaxf(rm, __shfl_xor_sync(0xffffffffu, rm, 8, 16));
            float mnew = fmaxf(m_i[i], rm);
            float p0 = __expf(s[i][0] - mnew);
            float p1 = __expf(s[i][1] - mnew);
            float p2 = __expf(s[i][2] - mnew);
            float p3 = __expf(s[i][3] - mnew);
            float rs = (p0 + p1) + (p2 + p3);
            rs += __shfl_xor_sync(0xffffffffu, rs, 1, 16);
            rs += __shfl_xor_sync(0xffffffffu, rs, 2, 16);
            rs += __shfl_xor_sync(0xffffffffu, rs, 4, 16);
            rs += __shfl_xor_sync(0xffffffffu, rs, 8, 16);
            float alpha = __expf(m_i[i] - mnew);
            l_i[i] = l_i[i] * alpha + rs;
            m_i[i] = mnew;
            o0a[i] *= alpha;
            o1a[i] *= alpha;
            float4 pv; pv.x = p0; pv.y = p1; pv.z = p2; pv.w = p3;
            *(float4*)&Ps[ty * 4 + i][tx * 4] = pv;
        }
        __syncthreads();

        // --- O += P * V^T : o[i][c] += sum_j Ps[row][j] * Vt[c][j] ---
#pragma unroll
        for (int j4 = 0; j4 < 64; j4 += 4) {
            float4 va = *(const float4*)&Vt[2 * tx][j4];
            float4 vb = *(const float4*)&Vt[2 * tx + 1][j4];
#pragma unroll
            for (int i = 0; i < 4; i++) {
                float4 p = *(const float4*)&Ps[ty * 4 + i][j4];
                o0a[i] = fmaf(p.x, va.x, o0a[i]);
                o0a[i] = fmaf(p.y, va.y, o0a[i]);
                o0a[i] = fmaf(p.z, va.z, o0a[i]);
                o0a[i] = fmaf(p.w, va.w, o0a[i]);
                o1a[i] = fmaf(p.x, vb.x, o1a[i]);
                o1a[i] = fmaf(p.y, vb.y, o1a[i]);
                o1a[i] = fmaf(p.z, vb.z, o1a[i]);
                o1a[i] = fmaf(p.w, vb.w, o1a[i]);
            }
        }
    }

    // Normalize and stage into Ps as [channel][row] for coalesced global stores
    __syncthreads();
#pragma unroll
    for (int i = 0; i < 4; i++) {
        float inv = 1.f / l_i[i];
        Ps[2 * tx][ty * 4 + i]     = o0a[i] * inv;
        Ps[2 * tx + 1][ty * 4 + i] = o1a[i] * inv;
    }
    __syncthreads();

    float* Ob = Oout + (size_t)(b * 128 + h * 32) * NPIX;
#pragma unroll
    for (int e = 0; e < 8; e++) {
        int idx = tid + e * 256;          // 0..2047
        int c = idx >> 6, r = idx & 63;
        Ob[c * NPIX + n0 + r] = Ps[c][r];
    }
}

// ---------------------------------------------------------------------------
// LePE 5x5 depthwise conv on v + residual add of attention output.
// One block per (b, c): stage padded 60x60 v plane in smem.
// ---------------------------------------------------------------------------
__global__ __launch_bounds__(256) void lepe_kernel(
    const float* __restrict__ lw,   // [C][25]
    const float* __restrict__ lb)   // [C]
{
    __shared__ float vs[60 * 60];
    const int bc = blockIdx.x;
    const int b = bc >> 7, c = bc & 127;
    const float* v = g_qkv + (size_t)(b * 384 + 256 + c) * NPIX;
    const int tid = threadIdx.x;

    for (int idx = tid; idx < 3600; idx += 256) {
        int yy = idx / 60 - 2, xx = idx % 60 - 2;
        vs[idx] = (yy >= 0 && yy < HH && xx >= 0 && xx < WW) ? v[yy * WW + xx] : 0.f;
    }
    float wk[25];
#pragma unroll
    for (int k = 0; k < 25; k++) wk[k] = lw[c * 25 + k];
    const float bb = lb[c];
    __syncthreads();

    const float* ab = g_att + (size_t)(b * 128 + c) * NPIX;
    float* pb = g_pre + (size_t)(b * 128 + c) * NPIX;
    for (int idx = tid; idx < NPIX; idx += 256) {
        int y = idx / WW, x = idx % WW;
        float acc = bb;
#pragma unroll
        for (int ky = 0; ky < 5; ky++)
#pragma unroll
            for (int kx = 0; kx < 5; kx++)
                acc = fmaf(vs[(y + ky) * 60 + (x + kx)], wk[ky * 5 + kx], acc);
        pb[idx] = acc + ab[idx];
    }
}

// ---------------------------------------------------------------------------

extern "C" void kernel_launch(void* const* d_in, const int* in_sizes, int n_in,
                              void* d_out, int out_size)
{
    const float* x      = (const float*)d_in[0];
    const float* qkv_w  = (const float*)d_in[1];
    const float* qkv_b  = (const float*)d_in[2];
    const float* lepe_w = (const float*)d_in[3];
    const float* lepe_b = (const float*)d_in[4];
    const float* proj_w = (const float*)d_in[5];
    const float* proj_b = (const float*)d_in[6];
    float* out = (float*)d_out;

    float *qkv_ptr, *pre_ptr;
    cudaGetSymbolAddress((void**)&qkv_ptr, g_qkv);
    cudaGetSymbolAddress((void**)&pre_ptr, g_pre);
    float* att_ptr;
    cudaGetSymbolAddress((void**)&att_ptr, g_att);

    // 1. qkv = qkv_w @ x + qkv_b   -> g_qkv [B][384][N]
    gemm1x1_kernel<<<dim3(NPIX / 64, 384 / 64, BATCH), 256>>>(
        qkv_w, qkv_b, x, qkv_ptr, 384);

    // 2. flash attention -> g_att [B][128][N]
    attn_kernel<<<dim3(NPIX / 64, BATCH * NH), 256>>>(att_ptr);

    // 3. lepe dwconv(v) + att -> g_pre
    lepe_kernel<<<dim3(BATCH * CCH), 256>>>(lepe_w, lepe_b);

    // 4. out = proj_w @ g_pre + proj_b -> d_out
    gemm1x1_kernel<<<dim3(NPIX / 64, 128 / 64, BATCH), 256>>>(
        proj_w, proj_b, pre_ptr, out, 128);
}